// round 15
// baseline (speedup 1.0000x reference)
#include <cuda_runtime.h>
#include <cstdint>

#define PAGE_SIZE 16
#define TILE 4096
#define THREADS 256
#define ITEMS 16
#define MAX_TILES 2048
#define WARPS_PER_TILE (THREADS / 32)   // 8

#define DT_I32 0
#define DT_I64 1
#define DT_F32 2

__device__ const char* g_seq;
__device__ const char* g_last;
__device__ const char* g_free;
__device__ int g_dtype;

__device__ int g_warp_sums[MAX_TILES * WARPS_PER_TILE];   // 64 KB
__device__ int g_tile_offs[MAX_TILES];
__device__ unsigned g_flags[MAX_TILES * (TILE / 32)];     // 1 MB packed flags

static __device__ __forceinline__ int flag_of(int s) {
    return ((s - 1) & (PAGE_SIZE - 1)) == 0 ? 1 : 0;  // (s-1)%16==0
}

// ---------------------------------------------------------------------------
// Kernel I: detect dtype {i32,i64,f32} + roles (seq < last < free by max).
// ---------------------------------------------------------------------------
__global__ void __launch_bounds__(256) k_init(const char* p0, const char* p1,
                                              const char* p2, int n) {
    __shared__ int smax[3];
    __shared__ unsigned s_odd, s_hi23;
    if (threadIdx.x < 3) smax[threadIdx.x] = 0;
    if (threadIdx.x == 0) { s_odd = 0u; s_hi23 = 0u; }
    __syncthreads();
    const char* ps[3] = {p0, p1, p2};
    const size_t stride = (size_t)n / 4096;   // 8-byte units
#pragma unroll
    for (int a = 0; a < 3; ++a) {
        const uint2* q = reinterpret_cast<const uint2*>(ps[a]);
        unsigned oddw = 0, hi23 = 0;
        int m = 0;
        for (int i = threadIdx.x; i < 2048; i += 256) {
            uint2 w = __ldg(q + (size_t)i * stride);
            oddw |= w.y;
            hi23 |= (w.x >> 23) | (w.y >> 23);
            m = max(m, (int)w.x);
        }
#pragma unroll
        for (int o = 16; o; o >>= 1) {
            m    = max(m, __shfl_down_sync(0xffffffffu, m, o));
            oddw |= __shfl_down_sync(0xffffffffu, oddw, o);
            hi23 |= __shfl_down_sync(0xffffffffu, hi23, o);
        }
        if ((threadIdx.x & 31) == 0) {
            atomicMax(&smax[a], m);
            atomicOr(&s_odd, oddw);
            atomicOr(&s_hi23, hi23);
        }
    }
    __syncthreads();
    if (threadIdx.x == 0) {
        int dt;
        if (s_odd == 0u) dt = DT_I64;
        else if (s_hi23 != 0u) dt = DT_F32;
        else dt = DT_I32;
        const int m0 = smax[0], m1 = smax[1], m2 = smax[2];
        const int seqi  = (m0 < m1 && m0 < m2) ? 0 : ((m1 < m2) ? 1 : 2);
        const int freei = (m0 > m1 && m0 > m2) ? 0 : ((m1 > m2) ? 1 : 2);
        const int lasti = 3 - seqi - freei;
        g_seq  = ps[seqi];
        g_last = ps[lasti];
        g_free = ps[freei];
        g_dtype = dt;
    }
}

template <int DT>
static __device__ __forceinline__ int4 fetch4(const char* p, size_t idx) {
    if (DT == DT_I64) {
        const longlong2* q = reinterpret_cast<const longlong2*>(p) + (idx >> 1);
        longlong2 a = __ldg(q), b = __ldg(q + 1);
        return make_int4((int)a.x, (int)a.y, (int)b.x, (int)b.y);
    } else if (DT == DT_F32) {
        float4 v = __ldg(reinterpret_cast<const float4*>(p) + (idx >> 2));
        return make_int4((int)v.x, (int)v.y, (int)v.z, (int)v.w);
    } else {
        return __ldg(reinterpret_cast<const int4*>(p) + (idx >> 2));
    }
}
template <int DT>
static __device__ __forceinline__ int fetch1(const char* p, int idx) {
    if (DT == DT_I64) return (int)__ldg(reinterpret_cast<const long long*>(p) + idx);
    if (DT == DT_F32) return (int)__ldg(reinterpret_cast<const float*>(p) + idx);
    return __ldg(reinterpret_cast<const int*>(p) + idx);
}

// ---------------------------------------------------------------------------
// Kernel 1: upsweep — packed flags + PER-WARP sums. No shared, no barriers.
// ---------------------------------------------------------------------------
template <int DT>
static __device__ __forceinline__ void upsweep_body() {
    const char* seq = g_seq;
    const int tile = blockIdx.x;
    const size_t base = (size_t)tile * TILE + threadIdx.x * ITEMS;

    unsigned m16 = 0;
#pragma unroll
    for (int j = 0; j < ITEMS / 4; ++j) {
        int4 v = fetch4<DT>(seq, base + 4 * j);
        m16 |= (unsigned)flag_of(v.x) << (4 * j + 0);
        m16 |= (unsigned)flag_of(v.y) << (4 * j + 1);
        m16 |= (unsigned)flag_of(v.z) << (4 * j + 2);
        m16 |= (unsigned)flag_of(v.w) << (4 * j + 3);
    }
    // publish packed flags: two threads per 32-bit word
    const unsigned partner = __shfl_xor_sync(0xffffffffu, m16, 1);
    if ((threadIdx.x & 1) == 0)
        g_flags[tile * (TILE / 32) + (threadIdx.x >> 1)] = m16 | (partner << 16);

    // warp reduce popc -> per-warp sum (no block reduce)
    int c = __popc(m16);
#pragma unroll
    for (int o = 16; o; o >>= 1) c += __shfl_down_sync(0xffffffffu, c, o);
    if ((threadIdx.x & 31) == 0)
        g_warp_sums[tile * WARPS_PER_TILE + (threadIdx.x >> 5)] = c;
}
__global__ void __launch_bounds__(THREADS) k_upsweep() {
    const int dt = g_dtype;
    if (dt == DT_I64) upsweep_body<DT_I64>();
    else if (dt == DT_F32) upsweep_body<DT_F32>();
    else upsweep_body<DT_I32>();
}

// ---------------------------------------------------------------------------
// Kernel 2: spine — derive tile sums from warp sums, exclusive scan of tiles.
//   One block, 1024 threads, 2 tiles each (16 warp-sum ints = 4 int4 loads).
// ---------------------------------------------------------------------------
__global__ void __launch_bounds__(1024) k_spine(int num_tiles) {
    __shared__ int s[1024];
    const int t = threadIdx.x;
    int a = 0, b = 0;
    if (2 * t < num_tiles) {
        const int4* q = reinterpret_cast<const int4*>(
            &g_warp_sums[2 * t * WARPS_PER_TILE]);
        int4 a0 = q[0], a1 = q[1], a2 = q[2], a3 = q[3];
        a = a0.x + a0.y + a0.z + a0.w + a1.x + a1.y + a1.z + a1.w;
        b = a2.x + a2.y + a2.z + a2.w + a3.x + a3.y + a3.z + a3.w;
    }
    const int mysum = a + b;
    s[t] = mysum;
    __syncthreads();
#pragma unroll
    for (int o = 1; o < 1024; o <<= 1) {
        const int u = (t >= o) ? s[t - o] : 0;
        __syncthreads();
        s[t] += u;
        __syncthreads();
    }
    const int excl = s[t] - mysum;
    if (2 * t < num_tiles) {
        g_tile_offs[2 * t] = excl;
        if (2 * t + 1 < num_tiles) g_tile_offs[2 * t + 1] = excl + a;
    }
}

// ---------------------------------------------------------------------------
// Kernel 3: downsweep — BARRIER-FREE. Flags from bitmask; per-warp prefix
//   from g_tile_offs + lower warp sums; in-warp shfl scan.
// ---------------------------------------------------------------------------
template <int DT>
static __device__ __forceinline__ void downsweep_body(float* __restrict__ out) {
    const char* last  = g_last;
    const char* freep = g_free;
    const int tile = blockIdx.x;
    const size_t base = (size_t)tile * TILE + threadIdx.x * ITEMS;
    const int lane = threadIdx.x & 31, wid = threadIdx.x >> 5;

    // issue all loads up front: flag word, warp sums, tile offset, last tile
    const unsigned w =
        __ldg(&g_flags[tile * (TILE / 32) + (threadIdx.x >> 1)]);
    const int wsum = (lane < WARPS_PER_TILE)
        ? __ldg(&g_warp_sums[tile * WARPS_PER_TILE + lane]) : 0;
    const int tile_off = __ldg(&g_tile_offs[tile]);
    int4 l[ITEMS / 4];
#pragma unroll
    for (int j = 0; j < ITEMS / 4; ++j) l[j] = fetch4<DT>(last, base + 4 * j);

    const unsigned m16 = (w >> ((threadIdx.x & 1) * 16)) & 0xFFFFu;
    const int c = __popc(m16);

    // warp-exclusive offset within tile: sum of warp sums with index < wid
    int v = (lane < wid) ? wsum : 0;
#pragma unroll
    for (int o = 4; o; o >>= 1) v += __shfl_down_sync(0xffffffffu, v, o);
    const int warp_excl = __shfl_sync(0xffffffffu, v, 0);

    // in-warp exclusive scan of per-thread counts
    int incl = c;
#pragma unroll
    for (int o = 1; o < 32; o <<= 1) {
        const int nv = __shfl_up_sync(0xffffffffu, incl, o);
        if (lane >= o) incl += nv;
    }

    int prefix = tile_off + warp_excl + (incl - c);

    float4* po = reinterpret_cast<float4*>(out + base);
#pragma unroll
    for (int j = 0; j < ITEMS / 4; ++j) {
        int vals[4];
        const int lv[4] = {l[j].x, l[j].y, l[j].z, l[j].w};
#pragma unroll
        for (int k = 0; k < 4; ++k) {
            if ((m16 >> (4 * j + k)) & 1u) {
                vals[k] = fetch1<DT>(freep, prefix) * PAGE_SIZE;
                ++prefix;
            } else {
                vals[k] = lv[k] + 1;
            }
        }
        float4 o4;
        o4.x = (float)vals[0]; o4.y = (float)vals[1];
        o4.z = (float)vals[2]; o4.w = (float)vals[3];
        po[j] = o4;
    }
}
__global__ void __launch_bounds__(THREADS) k_downsweep(float* __restrict__ out) {
    const int dt = g_dtype;
    if (dt == DT_I64) downsweep_body<DT_I64>(out);
    else if (dt == DT_F32) downsweep_body<DT_F32>(out);
    else downsweep_body<DT_I32>(out);
}

// ---------------------------------------------------------------------------
extern "C" void kernel_launch(void* const* d_in, const int* in_sizes, int n_in,
                              void* d_out, int out_size) {
    const char* p0 = (const char*)d_in[0];
    const char* p1 = (const char*)d_in[1];
    const char* p2 = (const char*)d_in[2];
    float* out = (float*)d_out;
    const int n = in_sizes[0];
    const int num_tiles = n / TILE;   // 2048

    k_init<<<1, 256>>>(p0, p1, p2, n);
    k_upsweep<<<num_tiles, THREADS>>>();
    k_spine<<<1, 1024>>>(num_tiles);
    k_downsweep<<<num_tiles, THREADS>>>(out);
}

// round 17
// speedup vs baseline: 1.0009x; 1.0009x over previous
#include <cuda_runtime.h>
#include <cstdint>

#define PAGE_SIZE 16
#define TILE 4096
#define THREADS 256
#define MAX_TILES 2048
#define WARPS_PER_TILE 8          // 512 items per warp segment

#define DT_I32 0
#define DT_I64 1
#define DT_F32 2

__device__ const char* g_seq;
__device__ const char* g_last;
__device__ const char* g_free;
__device__ int g_dtype;
__device__ unsigned g_done;

__device__ int g_warp_sums[MAX_TILES * WARPS_PER_TILE];   // 64 KB
__device__ int g_tile_offs[MAX_TILES];
__device__ unsigned g_flags[MAX_TILES * (TILE / 32)];     // 1 MB packed flags

static __device__ __forceinline__ int flag_of(int s) {
    return ((s - 1) & (PAGE_SIZE - 1)) == 0 ? 1 : 0;  // (s-1)%16==0
}

// ---------------------------------------------------------------------------
// Kernel I: detect dtype {i32,i64,f32} + roles; reset done-counter.
// ---------------------------------------------------------------------------
__global__ void __launch_bounds__(256) k_init(const char* p0, const char* p1,
                                              const char* p2, int n) {
    if (threadIdx.x == 0) g_done = 0u;
    __shared__ int smax[3];
    __shared__ unsigned s_odd, s_hi23;
    if (threadIdx.x < 3) smax[threadIdx.x] = 0;
    if (threadIdx.x == 0) { s_odd = 0u; s_hi23 = 0u; }
    __syncthreads();
    const char* ps[3] = {p0, p1, p2};
    const size_t stride = (size_t)n / 4096;   // 8-byte units
#pragma unroll
    for (int a = 0; a < 3; ++a) {
        const uint2* q = reinterpret_cast<const uint2*>(ps[a]);
        unsigned oddw = 0, hi23 = 0;
        int m = 0;
        for (int i = threadIdx.x; i < 2048; i += 256) {
            uint2 w = __ldg(q + (size_t)i * stride);
            oddw |= w.y;
            hi23 |= (w.x >> 23) | (w.y >> 23);
            m = max(m, (int)w.x);
        }
#pragma unroll
        for (int o = 16; o; o >>= 1) {
            m    = max(m, __shfl_down_sync(0xffffffffu, m, o));
            oddw |= __shfl_down_sync(0xffffffffu, oddw, o);
            hi23 |= __shfl_down_sync(0xffffffffu, hi23, o);
        }
        if ((threadIdx.x & 31) == 0) {
            atomicMax(&smax[a], m);
            atomicOr(&s_odd, oddw);
            atomicOr(&s_hi23, hi23);
        }
    }
    __syncthreads();
    if (threadIdx.x == 0) {
        int dt;
        if (s_odd == 0u) dt = DT_I64;
        else if (s_hi23 != 0u) dt = DT_F32;
        else dt = DT_I32;
        const int m0 = smax[0], m1 = smax[1], m2 = smax[2];
        const int seqi  = (m0 < m1 && m0 < m2) ? 0 : ((m1 < m2) ? 1 : 2);
        const int freei = (m0 > m1 && m0 > m2) ? 0 : ((m1 > m2) ? 1 : 2);
        const int lasti = 3 - seqi - freei;
        g_seq  = ps[seqi];
        g_last = ps[lasti];
        g_free = ps[freei];
        g_dtype = dt;
    }
}

template <int DT>
static __device__ __forceinline__ int4 fetch4(const char* p, size_t idx) {
    if (DT == DT_I64) {
        const longlong2* q = reinterpret_cast<const longlong2*>(p) + (idx >> 1);
        longlong2 a = __ldg(q), b = __ldg(q + 1);
        return make_int4((int)a.x, (int)a.y, (int)b.x, (int)b.y);
    } else if (DT == DT_F32) {
        float4 v = __ldg(reinterpret_cast<const float4*>(p) + (idx >> 2));
        return make_int4((int)v.x, (int)v.y, (int)v.z, (int)v.w);
    } else {
        return __ldg(reinterpret_cast<const int4*>(p) + (idx >> 2));
    }
}
template <int DT>
static __device__ __forceinline__ int fetch1(const char* p, int idx) {
    if (DT == DT_I64) return (int)__ldg(reinterpret_cast<const long long*>(p) + idx);
    if (DT == DT_F32) return (int)__ldg(reinterpret_cast<const float*>(p) + idx);
    return __ldg(reinterpret_cast<const int*>(p) + idx);
}

// ---------------------------------------------------------------------------
// Kernel 1: upsweep — COALESCED interleaved layout; packed flags + warp sums;
//   last block to finish scans the tile sums (threadfence-reduction spine).
//   Item (tile, warp w, group j, lane, k) lives at
//     tile*4096 + w*512 + j*128 + lane*4 + k          (j=0..3, k=0..3)
//   Flag bit (4j+k) of the thread's m16 corresponds to that item.
// ---------------------------------------------------------------------------
template <int DT>
static __device__ __forceinline__ void upsweep_body() {
    const char* seq = g_seq;
    const int tile = blockIdx.x;
    const int lane = threadIdx.x & 31, wid = threadIdx.x >> 5;
    const size_t seg = (size_t)tile * TILE + wid * 512;

    unsigned m16 = 0;
#pragma unroll
    for (int j = 0; j < 4; ++j) {
        int4 v = fetch4<DT>(seq, seg + j * 128 + lane * 4);
        m16 |= (unsigned)flag_of(v.x) << (4 * j + 0);
        m16 |= (unsigned)flag_of(v.y) << (4 * j + 1);
        m16 |= (unsigned)flag_of(v.z) << (4 * j + 2);
        m16 |= (unsigned)flag_of(v.w) << (4 * j + 3);
    }
    const unsigned partner = __shfl_xor_sync(0xffffffffu, m16, 1);
    if ((threadIdx.x & 1) == 0)
        g_flags[tile * (TILE / 32) + (threadIdx.x >> 1)] = m16 | (partner << 16);

    int c = __popc(m16);
#pragma unroll
    for (int o = 16; o; o >>= 1) c += __shfl_down_sync(0xffffffffu, c, o);
    if (lane == 0)
        g_warp_sums[tile * WARPS_PER_TILE + wid] = c;

    // ---- last block performs the spine scan (threadfence reduction) ----
    __threadfence();
    __shared__ int amLast;
    if (threadIdx.x == 0)
        amLast = (atomicAdd(&g_done, 1u) == gridDim.x - 1) ? 1 : 0;
    __syncthreads();
    if (amLast) {
        // thread t owns tiles [8t, 8t+8): 64 warp sums = 16 int4 loads
        const int t = threadIdx.x;
        const int4* q = reinterpret_cast<const int4*>(&g_warp_sums[t * 64]);
        int s[8];
        int tot = 0;
#pragma unroll
        for (int k = 0; k < 8; ++k) {
            int4 a = q[2 * k], b = q[2 * k + 1];
            s[k] = a.x + a.y + a.z + a.w + b.x + b.y + b.z + b.w;
            tot += s[k];
        }
        __shared__ int sh[256];
        sh[t] = tot;
        __syncthreads();
#pragma unroll
        for (int o = 1; o < 256; o <<= 1) {
            const int u = (t >= o) ? sh[t - o] : 0;
            __syncthreads();
            sh[t] += u;
            __syncthreads();
        }
        int run = sh[t] - tot;   // exclusive prefix of this thread's 8 tiles
#pragma unroll
        for (int k = 0; k < 8; ++k) {
            g_tile_offs[t * 8 + k] = run;
            run += s[k];
        }
    }
}
__global__ void __launch_bounds__(THREADS) k_upsweep() {
    const int dt = g_dtype;
    if (dt == DT_I64) upsweep_body<DT_I64>();
    else if (dt == DT_F32) upsweep_body<DT_F32>();
    else upsweep_body<DT_I32>();
}

// ---------------------------------------------------------------------------
// Kernel 2: downsweep — coalesced, barrier-free; ranks via ballots.
// ---------------------------------------------------------------------------
template <int DT>
static __device__ __forceinline__ void downsweep_body(float* __restrict__ out) {
    const char* last  = g_last;
    const char* freep = g_free;
    const int tile = blockIdx.x;
    const int lane = threadIdx.x & 31, wid = threadIdx.x >> 5;
    const size_t seg = (size_t)tile * TILE + wid * 512;

    // issue all loads up front
    const unsigned w =
        __ldg(&g_flags[tile * (TILE / 32) + (threadIdx.x >> 1)]);
    const int wsum = (lane < WARPS_PER_TILE)
        ? __ldg(&g_warp_sums[tile * WARPS_PER_TILE + lane]) : 0;
    const int tile_off = __ldg(&g_tile_offs[tile]);
    int4 l[4];
#pragma unroll
    for (int j = 0; j < 4; ++j)
        l[j] = fetch4<DT>(last, seg + j * 128 + lane * 4);

    const unsigned m16 = (w >> ((threadIdx.x & 1) * 16)) & 0xFFFFu;

    // warp-exclusive offset within tile (sum of warp sums with index < wid)
    int v = (lane < wid) ? wsum : 0;
#pragma unroll
    for (int o = 4; o; o >>= 1) v += __shfl_down_sync(0xffffffffu, v, o);
    const int warp_excl = __shfl_sync(0xffffffffu, v, 0);

    const unsigned lt = (lane == 0) ? 0u : (0xffffffffu >> (32 - lane));
    int run = tile_off + warp_excl;   // items before group j in this warp

#pragma unroll
    for (int j = 0; j < 4; ++j) {
        const unsigned nib = (m16 >> (4 * j)) & 0xFu;
        const unsigned b0 = __ballot_sync(0xffffffffu, nib & 1u);
        const unsigned b1 = __ballot_sync(0xffffffffu, nib & 2u);
        const unsigned b2 = __ballot_sync(0xffffffffu, nib & 4u);
        const unsigned b3 = __ballot_sync(0xffffffffu, nib & 8u);
        const int lane_excl = __popc(b0 & lt) + __popc(b1 & lt) +
                              __popc(b2 & lt) + __popc(b3 & lt);
        const int p = run + lane_excl;

        const int lv[4] = {l[j].x, l[j].y, l[j].z, l[j].w};
        int vals[4];
        // intra-nibble exclusive offsets
        const int o1 = (int)(nib & 1u);
        const int o2 = __popc((int)(nib & 3u));
        const int o3 = __popc((int)(nib & 7u));
        vals[0] = (nib & 1u) ? fetch1<DT>(freep, p)       * PAGE_SIZE : lv[0] + 1;
        vals[1] = (nib & 2u) ? fetch1<DT>(freep, p + o1)  * PAGE_SIZE : lv[1] + 1;
        vals[2] = (nib & 4u) ? fetch1<DT>(freep, p + o2)  * PAGE_SIZE : lv[2] + 1;
        vals[3] = (nib & 8u) ? fetch1<DT>(freep, p + o3)  * PAGE_SIZE : lv[3] + 1;

        float4 o4;
        o4.x = (float)vals[0]; o4.y = (float)vals[1];
        o4.z = (float)vals[2]; o4.w = (float)vals[3];
        reinterpret_cast<float4*>(out + seg + j * 128 + lane * 4)[0] = o4;

        run += __popc(b0) + __popc(b1) + __popc(b2) + __popc(b3);
    }
}
__global__ void __launch_bounds__(THREADS) k_downsweep(float* __restrict__ out) {
    const int dt = g_dtype;
    if (dt == DT_I64) downsweep_body<DT_I64>(out);
    else if (dt == DT_F32) downsweep_body<DT_F32>(out);
    else downsweep_body<DT_I32>(out);
}

// ---------------------------------------------------------------------------
extern "C" void kernel_launch(void* const* d_in, const int* in_sizes, int n_in,
                              void* d_out, int out_size) {
    const char* p0 = (const char*)d_in[0];
    const char* p1 = (const char*)d_in[1];
    const char* p2 = (const char*)d_in[2];
    float* out = (float*)d_out;
    const int n = in_sizes[0];
    const int num_tiles = n / TILE;   // 2048

    k_init<<<1, 256>>>(p0, p1, p2, n);
    k_upsweep<<<num_tiles, THREADS>>>();
    k_downsweep<<<num_tiles, THREADS>>>(out);
}